// round 12
// baseline (speedup 1.0000x reference)
#include <cuda_runtime.h>
#include <cuda_bf16.h>
#include <stdint.h>

// Problem constants (B=1, N=256, L=192, J=32, d2=1024, F=128)
#define LDIM 192
#define NDIM 256      // K of GEMM1
#define RDIM 6144     // L*J  (M=N of GEMM1)
#define D2   1024     // J*J  (K of GEMM2)
#define FDIM 128      // N of GEMM2
#define M2   36864    // L*L  (M of GEMM2)

// ---------------------------------------------------------------------------
// Scratch (__device__ globals). Interleaved hi/lo rows: one base pointer per
// matrix, lo part at constant byte offset LOB within each row.
//   g_A / g_B : row r (6144 rows) = [256 bf16 hi | 256 bf16 lo]   (1KB/row)
//   g_P       : row (36864 rows)  = [1024 hi | 1024 lo]           (4KB/row)
//   g_Wt      : row f (128 rows)  = [1024 hi | 1024 lo]           (4KB/row)
// ---------------------------------------------------------------------------
__device__ __nv_bfloat16 g_A[(size_t)RDIM * 512];
__device__ __nv_bfloat16 g_B[(size_t)RDIM * 512];
__device__ __nv_bfloat16 g_P[(size_t)M2 * 2048];
__device__ __nv_bfloat16 g_Wt[(size_t)FDIM * 2048];
__device__ float g_mu[M2];
__device__ float g_rs[M2];
__device__ float g_c1[FDIM];
__device__ float g_c2[FDIM];

// ---------------------------------------------------------------------------
// Family-portable PTX helpers (compute_103-safe: mma.sync / ldmatrix / cp.async)
// ---------------------------------------------------------------------------
__device__ __forceinline__ uint32_t smem_u32(const void* p) {
    uint32_t a;
    asm("{ .reg .u64 t; cvta.to.shared.u64 t, %1; cvt.u32.u64 %0, t; }" : "=r"(a) : "l"(p));
    return a;
}
__device__ __forceinline__ void cp16(uint32_t dst, const void* src) {
    asm volatile("cp.async.cg.shared.global [%0], [%1], 16;" :: "r"(dst), "l"(src) : "memory");
}
__device__ __forceinline__ void cp_commit() {
    asm volatile("cp.async.commit_group;" ::: "memory");
}
template <int N>
__device__ __forceinline__ void cp_wait() {
    asm volatile("cp.async.wait_group %0;" :: "n"(N) : "memory");
}
__device__ __forceinline__ void ldm4(uint32_t a[4], uint32_t addr) {
    asm volatile("ldmatrix.sync.aligned.m8n8.x4.shared.b16 {%0,%1,%2,%3}, [%4];"
                 : "=r"(a[0]), "=r"(a[1]), "=r"(a[2]), "=r"(a[3]) : "r"(addr));
}
__device__ __forceinline__ void ldm2(uint32_t b[2], uint32_t addr) {
    asm volatile("ldmatrix.sync.aligned.m8n8.x2.shared.b16 {%0,%1}, [%2];"
                 : "=r"(b[0]), "=r"(b[1]) : "r"(addr));
}
__device__ __forceinline__ void mma16816(float c[4], const uint32_t a[4], const uint32_t b[2]) {
    asm volatile(
        "mma.sync.aligned.m16n8k16.row.col.f32.bf16.bf16.f32 "
        "{%0,%1,%2,%3}, {%4,%5,%6,%7}, {%8,%9}, {%0,%1,%2,%3};"
        : "+f"(c[0]), "+f"(c[1]), "+f"(c[2]), "+f"(c[3])
        : "r"(a[0]), "r"(a[1]), "r"(a[2]), "r"(a[3]), "r"(b[0]), "r"(b[1]));
}

// SMEM tile: 128 rows x 16 bf16 (32B/row), 2x16B chunks.
// Swizzle: chunk bit XOR (r>>2)&1 -> conflict-free ldmatrix phases (R9 win).
__device__ __forceinline__ uint32_t sw(int r, int c2) {
    return (uint32_t)(r * 32 + ((c2 ^ ((r >> 2) & 1)) << 4));
}

// SMEM layout per stage (16 KB): Ah[0:4K) Al[4K:8K) Bh[8K:12K) Bl[12K:16K)
#define STAGE_BYTES 16384
#define NSTAGE 3
#define SMEM_BYTES  (NSTAGE * STAGE_BYTES)   // 48 KB static

// ---------------------------------------------------------------------------
// Shared mainloop: 128x128 CTA tile, 8 warps (2x4), warp tile 64x32,
// K-chunk 16, 3-stage cp.async ring, one barrier per chunk,
// 3-MMA bf16 hi/lo split, A-fragments SOFTWARE-PIPELINED (double-buffered:
// ldm4 for mt+1 issued before the 12 MMAs of mt -> LDS latency hidden).
// ROWB = row stride bytes (hi+lo), LOB = lo-part byte offset within row.
// ---------------------------------------------------------------------------
template <int ROWB, int LOB>
__device__ __forceinline__ void mainloop(
    uint32_t sb, int NC,
    const char* __restrict__ A, const char* __restrict__ B,
    float acc[4][4][4])
{
    const int tid = threadIdx.x, lane = tid & 31;
    const int wr = tid >> 7;           // warp row 0..1 (64 rows each)
    const int wc = (tid >> 5) & 3;     // warp col 0..3 (32 cols each)

    // global->smem: 1 uint4 per tile per thread (256 threads = 128 rows x 2 chunks)
    const int r = tid >> 1, c2 = tid & 1;
    const uint32_t so = sw(r, c2);
    const char* pA = A + (size_t)r * ROWB + c2 * 16;
    const char* pB = B + (size_t)r * ROWB + c2 * 16;

    // ldmatrix fragment base offsets (+512/+256 keep (r>>2)&1 parity).
    const uint32_t abase = sw(wr * 64 + (lane & 15), lane >> 4);
    const uint32_t bbase = sw(wc * 32 + (lane & 7), (lane >> 3) & 1);

#define ISSUE_CHUNK(ck, st) do {                                   \
        uint32_t _b = sb + (uint32_t)(st) * STAGE_BYTES;           \
        int _ko = (ck) * 32;                                       \
        cp16(_b + so,          pA + _ko);                          \
        cp16(_b + 4096u + so,  pA + LOB + _ko);                    \
        cp16(_b + 8192u + so,  pB + _ko);                          \
        cp16(_b + 12288u + so, pB + LOB + _ko);                    \
    } while (0)

    // prologue: chunks 0,1 -> stages 0,1
    ISSUE_CHUNK(0, 0); cp_commit();
    if (NC > 1) ISSUE_CHUNK(1, 1);
    cp_commit();

#pragma unroll 1
    for (int c = 0; c < NC; ++c) {
        const int st = c % NSTAGE;
        cp_wait<1>();          // chunk c resident
        __syncthreads();       // all warps done reading stage (c-1)%3

        const uint32_t Ab = sb + (uint32_t)st * STAGE_BYTES;
        const uint32_t Bb = Ab + 8192u;

        // B fragments first
        uint32_t bh[4][2], bl[4][2];
#pragma unroll
        for (int nt = 0; nt < 4; ++nt) {
            ldm2(bh[nt], Bb + bbase + nt * 256u);
            ldm2(bl[nt], Bb + 4096u + bbase + nt * 256u);
        }

        // prefetch chunk c+2 into stage (c+2)%3 == (c-1)%3 (safe: post-barrier)
        if (c + 2 < NC) ISSUE_CHUNK(c + 2, (c + 2) % NSTAGE);
        cp_commit();

        // A-fragment pipeline: preload mt=0, then load mt+1 before mt's MMAs.
        uint32_t ah[2][4], al[2][4];
        ldm4(ah[0], Ab + abase);
        ldm4(al[0], Ab + 4096u + abase);
#pragma unroll
        for (int mt = 0; mt < 4; ++mt) {
            const int cur = mt & 1;
            if (mt < 3) {
                ldm4(ah[cur ^ 1], Ab + abase + (mt + 1) * 512u);
                ldm4(al[cur ^ 1], Ab + 4096u + abase + (mt + 1) * 512u);
            }
#pragma unroll
            for (int nt = 0; nt < 4; ++nt) mma16816(acc[mt][nt], ah[cur], bh[nt]);  // hi*hi
#pragma unroll
            for (int nt = 0; nt < 4; ++nt) mma16816(acc[mt][nt], ah[cur], bl[nt]);  // hi*lo
#pragma unroll
            for (int nt = 0; nt < 4; ++nt) mma16816(acc[mt][nt], al[cur], bh[nt]);  // lo*hi
        }
    }
#undef ISSUE_CHUNK
}

// ---------------------------------------------------------------------------
// GEMM1: pair(6144x6144) = Xd^T Xw, K=256. Epilogue: LN stats per 32x32
// (i,l) block + raw pair stored hi/lo interleaved in GEMM2 layout.
// ---------------------------------------------------------------------------
__global__ __launch_bounds__(256, 2) void gemm1_mma() {
    __shared__ char smem[SMEM_BYTES];
    const uint32_t sb = smem_u32(smem);

    float acc[4][4][4];
#pragma unroll
    for (int a = 0; a < 4; ++a)
#pragma unroll
        for (int b = 0; b < 4; ++b)
#pragma unroll
            for (int d = 0; d < 4; ++d) acc[a][b][d] = 0.f;

    const int r0 = blockIdx.y * 128, c0 = blockIdx.x * 128;
    mainloop<1024, 512>(sb, NDIM / 16,
                        (const char*)g_A + (size_t)r0 * 1024,
                        (const char*)g_B + (size_t)c0 * 1024, acc);

    const int tid = threadIdx.x, lane = tid & 31;
    const int wr = tid >> 7, wc = (tid >> 5) & 3;

    // Warp covers rows wr*64..+63 (2 LN i-blocks), cols wc*32..+31 (1 l-block).
#pragma unroll
    for (int b = 0; b < 2; ++b) {
        float s = 0.f, q = 0.f;
#pragma unroll
        for (int mt2 = 0; mt2 < 2; ++mt2)
#pragma unroll
            for (int nt = 0; nt < 4; ++nt)
#pragma unroll
                for (int d = 0; d < 4; ++d) {
                    float v = acc[b * 2 + mt2][nt][d];
                    s += v;
                    q += v * v;
                }
#pragma unroll
        for (int o = 16; o; o >>= 1) {
            s += __shfl_xor_sync(0xFFFFFFFFu, s, o);
            q += __shfl_xor_sync(0xFFFFFFFFu, q, o);
        }
        const int i = blockIdx.y * 4 + wr * 2 + b;
        const int l = blockIdx.x * 4 + wc;
        if (lane == 0) {
            float mean = s * (1.0f / 1024.0f);
            float var = q * (1.0f / 1024.0f) - mean * mean;
            g_mu[i * LDIM + l] = mean;
            g_rs[i * LDIM + l] = rsqrtf(var + 1e-5f);
        }
        const size_t ro = (size_t)(i * LDIM + l) * 2048;   // interleaved row
#pragma unroll
        for (int mt2 = 0; mt2 < 2; ++mt2)
#pragma unroll
            for (int nt = 0; nt < 4; ++nt)
#pragma unroll
                for (int h = 0; h < 2; ++h) {
                    float v0 = acc[b * 2 + mt2][nt][h * 2 + 0];
                    float v1 = acc[b * 2 + mt2][nt][h * 2 + 1];
                    int j = mt2 * 16 + (lane >> 2) + 8 * h;
                    int m = nt * 8 + (lane & 3) * 2;
                    __nv_bfloat162 hh = __floats2bfloat162_rn(v0, v1);
                    *(uint32_t*)(g_P + ro + j * 32 + m) = *(uint32_t*)&hh;
                    __nv_bfloat162 ll = __floats2bfloat162_rn(
                        v0 - __bfloat162float(hh.x), v1 - __bfloat162float(hh.y));
                    *(uint32_t*)(g_P + ro + 1024 + j * 32 + m) = *(uint32_t*)&ll;
                }
    }
}

// ---------------------------------------------------------------------------
// GEMM2: out(36864x128) = pair @ Wp, K=1024. Epilogue: folded layernorm.
// ---------------------------------------------------------------------------
__global__ __launch_bounds__(256, 2) void gemm2_mma(float* __restrict__ out) {
    __shared__ char smem[SMEM_BYTES];
    const uint32_t sb = smem_u32(smem);

    float acc[4][4][4];
#pragma unroll
    for (int a = 0; a < 4; ++a)
#pragma unroll
        for (int b = 0; b < 4; ++b)
#pragma unroll
            for (int d = 0; d < 4; ++d) acc[a][b][d] = 0.f;

    const int row0 = blockIdx.x * 128;
    mainloop<4096, 2048>(sb, D2 / 16,
                         (const char*)g_P + (size_t)row0 * 4096,
                         (const char*)g_Wt, acc);

    const int tid = threadIdx.x, lane = tid & 31;
    const int wr = tid >> 7, wc = (tid >> 5) & 3;

    float c1v[4][2], c2v[4][2];
#pragma unroll
    for (int nt = 0; nt < 4; ++nt)
#pragma unroll
        for (int e = 0; e < 2; ++e) {
            int f = wc * 32 + nt * 8 + (lane & 3) * 2 + e;
            c1v[nt][e] = g_c1[f];
            c2v[nt][e] = g_c2[f];
        }
#pragma unroll
    for (int mt = 0; mt < 4; ++mt)
#pragma unroll
        for (int h = 0; h < 2; ++h) {
            int rr = row0 + wr * 64 + mt * 16 + (lane >> 2) + 8 * h;
            float rs = g_rs[rr];
            float tmu = rs * g_mu[rr];
#pragma unroll
            for (int nt = 0; nt < 4; ++nt) {
                float2 o;
                o.x = rs * acc[mt][nt][h * 2 + 0] - tmu * c1v[nt][0] + c2v[nt][0];
                o.y = rs * acc[mt][nt][h * 2 + 1] - tmu * c1v[nt][1] + c2v[nt][1];
                *(float2*)(out + (size_t)rr * FDIM + wc * 32 + nt * 8 + (lane & 3) * 2) = o;
            }
        }
}

// ---------------------------------------------------------------------------
// Prep: transpose+split x_down / x_down_w (256 x 6144 -> 6144 rows, hi|lo)
// ---------------------------------------------------------------------------
__global__ __launch_bounds__(256) void split_xt(const float* __restrict__ xd,
                                                const float* __restrict__ xw) {
    __shared__ float t[32][33];
    const float* src = blockIdx.z ? xw : xd;
    __nv_bfloat16* dst = blockIdx.z ? g_B : g_A;
    const int r0 = blockIdx.x * 32, n0 = blockIdx.y * 32;
    const int tx = threadIdx.x & 31, ty = threadIdx.x >> 5;
#pragma unroll
    for (int yy = 0; yy < 4; ++yy) {
        int n = n0 + ty + yy * 8;
        t[ty + yy * 8][tx] = src[(size_t)n * RDIM + r0 + tx];
    }
    __syncthreads();
#pragma unroll
    for (int yy = 0; yy < 4; ++yy) {
        int r = r0 + ty + yy * 8;
        float v = t[tx][ty + yy * 8];
        __nv_bfloat16 h = __float2bfloat16(v);
        dst[(size_t)r * 512 + n0 + tx] = h;
        dst[(size_t)r * 512 + 256 + n0 + tx] = __float2bfloat16(v - __bfloat162float(h));
    }
}

// Prep: Wp^T = (a2 (.) W)^T, split hi/lo interleaved, layout [f][k-hi | k-lo]
__global__ __launch_bounds__(256) void split_wt(const float* __restrict__ W,
                                                const float* __restrict__ a2) {
    __shared__ float t[32][33];
    const int k0 = blockIdx.x * 32, f0 = blockIdx.y * 32;
    const int tx = threadIdx.x & 31, ty = threadIdx.x >> 5;
#pragma unroll
    for (int yy = 0; yy < 4; ++yy) {
        int k = k0 + ty + yy * 8;
        t[ty + yy * 8][tx] = a2[k] * W[(size_t)k * FDIM + f0 + tx];
    }
    __syncthreads();
#pragma unroll
    for (int yy = 0; yy < 4; ++yy) {
        int f = f0 + ty + yy * 8;
        float v = t[tx][ty + yy * 8];
        __nv_bfloat16 h = __float2bfloat16(v);
        g_Wt[(size_t)f * 2048 + k0 + tx] = h;
        g_Wt[(size_t)f * 2048 + 1024 + k0 + tx] = __float2bfloat16(v - __bfloat162float(h));
    }
}

// Prep: c1[f] = sum_k a2[k] W[k][f];  c2[f] = sum_k b2[k] W[k][f] + b[f]
__global__ void prep_c_kernel(const float* __restrict__ a2, const float* __restrict__ b2,
                              const float* __restrict__ W, const float* __restrict__ b) {
    int f = threadIdx.x;  // 0..127
    float c1 = 0.f, c2 = 0.f;
#pragma unroll 8
    for (int k = 0; k < D2; ++k) {
        float w = W[k * FDIM + f];
        c1 += a2[k] * w;
        c2 += b2[k] * w;
    }
    g_c1[f] = c1;
    g_c2[f] = c2 + b[f];
}

// ---------------------------------------------------------------------------
extern "C" void kernel_launch(void* const* d_in, const int* in_sizes, int n_in,
                              void* d_out, int out_size) {
    const float* x_down   = (const float*)d_in[0];  // (1,256,192,32)
    const float* x_down_w = (const float*)d_in[1];
    const float* a2       = (const float*)d_in[2];  // (1024,)
    const float* b2       = (const float*)d_in[3];
    const float* W        = (const float*)d_in[4];  // (1024,128)
    const float* b        = (const float*)d_in[5];  // (128,)
    float* out = (float*)d_out;                     // (1,192,192,128)

    // Keep the L1/smem carveout high so two 48KB-smem CTAs co-reside per SM.
    cudaFuncSetAttribute(gemm1_mma, cudaFuncAttributePreferredSharedMemoryCarveout, 100);
    cudaFuncSetAttribute(gemm2_mma, cudaFuncAttributePreferredSharedMemoryCarveout, 100);

    split_xt<<<dim3(RDIM / 32, NDIM / 32, 2), 256>>>(x_down, x_down_w);
    split_wt<<<dim3(D2 / 32, FDIM / 32), 256>>>(W, a2);
    prep_c_kernel<<<1, 128>>>(a2, b2, W, b);
    gemm1_mma<<<dim3(48, 48), 256>>>();
    gemm2_mma<<<M2 / 128, 256>>>(out);
}

// round 13
// speedup vs baseline: 1.4967x; 1.4967x over previous
#include <cuda_runtime.h>
#include <cuda_fp16.h>
#include <stdint.h>

// Problem constants (B=1, N=256, L=192, J=32, d2=1024, F=128)
#define LDIM 192
#define NDIM 256      // K of GEMM1
#define RDIM 6144     // L*J  (M=N of GEMM1)
#define D2   1024     // J*J  (K of GEMM2)
#define FDIM 128      // N of GEMM2
#define M2   36864    // L*L  (M of GEMM2)

// ---------------------------------------------------------------------------
// Scratch (__device__ globals).
//   g_A  : x_down^T   single fp16, row r = 256 fp16 (512 B)
//   g_B  : x_down_w^T hi/lo fp16, row r = [256 hi | 256 lo] (1 KB)
//   g_P  : pair       single fp16, row (i*192+l) = 1024 fp16 (2 KB)
//   g_Wt : (a2*W)^T   hi/lo fp16, row f = [1024 hi | 1024 lo] (4 KB)
// ---------------------------------------------------------------------------
__device__ __half g_A[(size_t)RDIM * 256];
__device__ __half g_B[(size_t)RDIM * 512];
__device__ __half g_P[(size_t)M2 * 1024];
__device__ __half g_Wt[(size_t)FDIM * 2048];
__device__ float g_mu[M2];
__device__ float g_rs[M2];
__device__ float g_c1[FDIM];
__device__ float g_c2[FDIM];

// ---------------------------------------------------------------------------
// Family-portable PTX helpers (compute_103-safe)
// ---------------------------------------------------------------------------
__device__ __forceinline__ uint32_t smem_u32(const void* p) {
    uint32_t a;
    asm("{ .reg .u64 t; cvta.to.shared.u64 t, %1; cvt.u32.u64 %0, t; }" : "=r"(a) : "l"(p));
    return a;
}
__device__ __forceinline__ void cp16(uint32_t dst, const void* src) {
    asm volatile("cp.async.cg.shared.global [%0], [%1], 16;" :: "r"(dst), "l"(src) : "memory");
}
__device__ __forceinline__ void cp_commit() {
    asm volatile("cp.async.commit_group;" ::: "memory");
}
template <int N>
__device__ __forceinline__ void cp_wait() {
    asm volatile("cp.async.wait_group %0;" :: "n"(N) : "memory");
}
__device__ __forceinline__ void ldm4(uint32_t a[4], uint32_t addr) {
    asm volatile("ldmatrix.sync.aligned.m8n8.x4.shared.b16 {%0,%1,%2,%3}, [%4];"
                 : "=r"(a[0]), "=r"(a[1]), "=r"(a[2]), "=r"(a[3]) : "r"(addr));
}
__device__ __forceinline__ void ldm2(uint32_t b[2], uint32_t addr) {
    asm volatile("ldmatrix.sync.aligned.m8n8.x2.shared.b16 {%0,%1}, [%2];"
                 : "=r"(b[0]), "=r"(b[1]) : "r"(addr));
}
// fp16 inputs, fp32 accumulate
__device__ __forceinline__ void mma16816(float c[4], const uint32_t a[4], const uint32_t b[2]) {
    asm volatile(
        "mma.sync.aligned.m16n8k16.row.col.f32.f16.f16.f32 "
        "{%0,%1,%2,%3}, {%4,%5,%6,%7}, {%8,%9}, {%0,%1,%2,%3};"
        : "+f"(c[0]), "+f"(c[1]), "+f"(c[2]), "+f"(c[3])
        : "r"(a[0]), "r"(a[1]), "r"(a[2]), "r"(a[3]), "r"(b[0]), "r"(b[1]));
}

// SMEM tile: 128 rows x 16 fp16 (32B/row), 2x16B chunks.
// Swizzle: chunk bit XOR (r>>2)&1 -> conflict-free ldmatrix phases (R9 win).
__device__ __forceinline__ uint32_t sw(int r, int c2) {
    return (uint32_t)(r * 32 + ((c2 ^ ((r >> 2) & 1)) << 4));
}

// SMEM layout per stage (12 KB): A[0:4K) Bh[4K:8K) Bl[8K:12K)
#define STAGE_BYTES 12288
#define NSTAGE 4
#define SMEM_BYTES  (NSTAGE * STAGE_BYTES)   // 48 KB static

// ---------------------------------------------------------------------------
// Shared mainloop: 128x128 CTA tile, 8 warps (2x4), warp tile 64x32,
// K-chunk 16, 4-stage cp.async ring (prefetch distance 3), one barrier/chunk,
// 2-MMA fp16 split: A single fp16, B = bh + bl.
// ---------------------------------------------------------------------------
template <int AROWB, int BROWB, int BLOB>
__device__ __forceinline__ void mainloop(
    uint32_t sb, int NC,
    const char* __restrict__ A, const char* __restrict__ B,
    float acc[4][4][4])
{
    const int tid = threadIdx.x, lane = tid & 31;
    const int wr = tid >> 7;           // warp row 0..1 (64 rows each)
    const int wc = (tid >> 5) & 3;     // warp col 0..3 (32 cols each)

    // global->smem: 3 x 16B per thread (256 threads = 128 rows x 2 chunks)
    const int r = tid >> 1, c2 = tid & 1;
    const uint32_t so = sw(r, c2);
    const char* pA = A + (size_t)r * AROWB + c2 * 16;
    const char* pB = B + (size_t)r * BROWB + c2 * 16;

    // ldmatrix fragment base offsets (+512/+256 keep (r>>2)&1 parity).
    const uint32_t abase = sw(wr * 64 + (lane & 15), lane >> 4);
    const uint32_t bbase = sw(wc * 32 + (lane & 7), (lane >> 3) & 1);

#define ISSUE_CHUNK(ck, st) do {                                   \
        uint32_t _b = sb + (uint32_t)(st) * STAGE_BYTES;           \
        int _ko = (ck) * 32;                                       \
        cp16(_b + so,          pA + _ko);                          \
        cp16(_b + 4096u + so,  pB + _ko);                          \
        cp16(_b + 8192u + so,  pB + BLOB + _ko);                   \
    } while (0)

    // prologue: chunks 0,1,2 -> stages 0,1,2
    ISSUE_CHUNK(0, 0); cp_commit();
    if (NC > 1) ISSUE_CHUNK(1, 1);
    cp_commit();
    if (NC > 2) ISSUE_CHUNK(2, 2);
    cp_commit();

#pragma unroll 1
    for (int c = 0; c < NC; ++c) {
        const int st = c & 3;
        cp_wait<2>();          // chunk c resident (<=2 younger groups pending)
        __syncthreads();       // all warps done reading stage (c-1)&3

        const uint32_t Ab = sb + (uint32_t)st * STAGE_BYTES;
        const uint32_t Bbh = Ab + 4096u;
        const uint32_t Bbl = Ab + 8192u;

        // B fragments first
        uint32_t bh[4][2], bl[4][2];
#pragma unroll
        for (int nt = 0; nt < 4; ++nt) {
            ldm2(bh[nt], Bbh + bbase + nt * 256u);
            ldm2(bl[nt], Bbl + bbase + nt * 256u);
        }

        // prefetch chunk c+3 into stage (c+3)&3 == (c-1)&3 (safe: post-barrier)
        if (c + 3 < NC) ISSUE_CHUNK(c + 3, (c + 3) & 3);
        cp_commit();

#pragma unroll
        for (int mt = 0; mt < 4; ++mt) {
            uint32_t a[4];
            ldm4(a, Ab + abase + mt * 512u);
#pragma unroll
            for (int nt = 0; nt < 4; ++nt) mma16816(acc[mt][nt], a, bh[nt]);  // a*bhi
#pragma unroll
            for (int nt = 0; nt < 4; ++nt) mma16816(acc[mt][nt], a, bl[nt]);  // a*blo
        }
    }
#undef ISSUE_CHUNK
}

// ---------------------------------------------------------------------------
// GEMM1: pair(6144x6144) = Xd^T Xw, K=256. Epilogue: LN stats per 32x32
// (i,l) block + pair stored single fp16 in GEMM2 layout.
// ---------------------------------------------------------------------------
__global__ __launch_bounds__(256, 2) void gemm1_mma() {
    __shared__ char smem[SMEM_BYTES];
    const uint32_t sb = smem_u32(smem);

    float acc[4][4][4];
#pragma unroll
    for (int a = 0; a < 4; ++a)
#pragma unroll
        for (int b = 0; b < 4; ++b)
#pragma unroll
            for (int d = 0; d < 4; ++d) acc[a][b][d] = 0.f;

    const int r0 = blockIdx.y * 128, c0 = blockIdx.x * 128;
    mainloop<512, 1024, 512>(sb, NDIM / 16,
                             (const char*)g_A + (size_t)r0 * 512,
                             (const char*)g_B + (size_t)c0 * 1024, acc);

    const int tid = threadIdx.x, lane = tid & 31;
    const int wr = tid >> 7, wc = (tid >> 5) & 3;

    // Warp covers rows wr*64..+63 (2 LN i-blocks), cols wc*32..+31 (1 l-block).
#pragma unroll
    for (int b = 0; b < 2; ++b) {
        float s = 0.f, q = 0.f;
#pragma unroll
        for (int mt2 = 0; mt2 < 2; ++mt2)
#pragma unroll
            for (int nt = 0; nt < 4; ++nt)
#pragma unroll
                for (int d = 0; d < 4; ++d) {
                    float v = acc[b * 2 + mt2][nt][d];
                    s += v;
                    q += v * v;
                }
#pragma unroll
        for (int o = 16; o; o >>= 1) {
            s += __shfl_xor_sync(0xFFFFFFFFu, s, o);
            q += __shfl_xor_sync(0xFFFFFFFFu, q, o);
        }
        const int i = blockIdx.y * 4 + wr * 2 + b;
        const int l = blockIdx.x * 4 + wc;
        if (lane == 0) {
            float mean = s * (1.0f / 1024.0f);
            float var = q * (1.0f / 1024.0f) - mean * mean;
            g_mu[i * LDIM + l] = mean;
            g_rs[i * LDIM + l] = rsqrtf(var + 1e-5f);
        }
        const size_t ro = (size_t)(i * LDIM + l) * 1024;   // fp16 row
#pragma unroll
        for (int mt2 = 0; mt2 < 2; ++mt2)
#pragma unroll
            for (int nt = 0; nt < 4; ++nt)
#pragma unroll
                for (int h = 0; h < 2; ++h) {
                    float v0 = acc[b * 2 + mt2][nt][h * 2 + 0];
                    float v1 = acc[b * 2 + mt2][nt][h * 2 + 1];
                    int j = mt2 * 16 + (lane >> 2) + 8 * h;
                    int m = nt * 8 + (lane & 3) * 2;
                    __half2 hh = __floats2half2_rn(v0, v1);
                    *(uint32_t*)(g_P + ro + j * 32 + m) = *(uint32_t*)&hh;
                }
    }
}

// ---------------------------------------------------------------------------
// GEMM2: out(36864x128) = pair @ Wp, K=1024. Epilogue: folded layernorm.
// A = pair (single fp16), B = Wt (hi/lo).
// ---------------------------------------------------------------------------
__global__ __launch_bounds__(256, 2) void gemm2_mma(float* __restrict__ out) {
    __shared__ char smem[SMEM_BYTES];
    const uint32_t sb = smem_u32(smem);

    float acc[4][4][4];
#pragma unroll
    for (int a = 0; a < 4; ++a)
#pragma unroll
        for (int b = 0; b < 4; ++b)
#pragma unroll
            for (int d = 0; d < 4; ++d) acc[a][b][d] = 0.f;

    const int row0 = blockIdx.x * 128;
    mainloop<2048, 4096, 2048>(sb, D2 / 16,
                               (const char*)g_P + (size_t)row0 * 2048,
                               (const char*)g_Wt, acc);

    const int tid = threadIdx.x, lane = tid & 31;
    const int wr = tid >> 7, wc = (tid >> 5) & 3;

    float c1v[4][2], c2v[4][2];
#pragma unroll
    for (int nt = 0; nt < 4; ++nt)
#pragma unroll
        for (int e = 0; e < 2; ++e) {
            int f = wc * 32 + nt * 8 + (lane & 3) * 2 + e;
            c1v[nt][e] = g_c1[f];
            c2v[nt][e] = g_c2[f];
        }
#pragma unroll
    for (int mt = 0; mt < 4; ++mt)
#pragma unroll
        for (int h = 0; h < 2; ++h) {
            int rr = row0 + wr * 64 + mt * 16 + (lane >> 2) + 8 * h;
            float rs = g_rs[rr];
            float tmu = rs * g_mu[rr];
#pragma unroll
            for (int nt = 0; nt < 4; ++nt) {
                float2 o;
                o.x = rs * acc[mt][nt][h * 2 + 0] - tmu * c1v[nt][0] + c2v[nt][0];
                o.y = rs * acc[mt][nt][h * 2 + 1] - tmu * c1v[nt][1] + c2v[nt][1];
                *(float2*)(out + (size_t)rr * FDIM + wc * 32 + nt * 8 + (lane & 3) * 2) = o;
            }
        }
}

// ---------------------------------------------------------------------------
// Prep: transpose x_down / x_down_w (256 x 6144 -> 6144 rows).
// z=0: x_down -> g_A single fp16.  z=1: x_down_w -> g_B fp16 hi|lo.
// ---------------------------------------------------------------------------
__global__ __launch_bounds__(256) void split_xt(const float* __restrict__ xd,
                                                const float* __restrict__ xw) {
    __shared__ float t[32][33];
    const float* src = blockIdx.z ? xw : xd;
    const int r0 = blockIdx.x * 32, n0 = blockIdx.y * 32;
    const int tx = threadIdx.x & 31, ty = threadIdx.x >> 5;
#pragma unroll
    for (int yy = 0; yy < 4; ++yy) {
        int n = n0 + ty + yy * 8;
        t[ty + yy * 8][tx] = src[(size_t)n * RDIM + r0 + tx];
    }
    __syncthreads();
#pragma unroll
    for (int yy = 0; yy < 4; ++yy) {
        int r = r0 + ty + yy * 8;
        float v = t[tx][ty + yy * 8];
        __half h = __float2half_rn(v);
        if (blockIdx.z == 0) {
            g_A[(size_t)r * 256 + n0 + tx] = h;
        } else {
            g_B[(size_t)r * 512 + n0 + tx] = h;
            g_B[(size_t)r * 512 + 256 + n0 + tx] = __float2half_rn(v - __half2float(h));
        }
    }
}

// Prep: Wp^T = (a2 (.) W)^T, fp16 hi/lo, layout [f][k-hi | k-lo]
__global__ __launch_bounds__(256) void split_wt(const float* __restrict__ W,
                                                const float* __restrict__ a2) {
    __shared__ float t[32][33];
    const int k0 = blockIdx.x * 32, f0 = blockIdx.y * 32;
    const int tx = threadIdx.x & 31, ty = threadIdx.x >> 5;
#pragma unroll
    for (int yy = 0; yy < 4; ++yy) {
        int k = k0 + ty + yy * 8;
        t[ty + yy * 8][tx] = a2[k] * W[(size_t)k * FDIM + f0 + tx];
    }
    __syncthreads();
#pragma unroll
    for (int yy = 0; yy < 4; ++yy) {
        int f = f0 + ty + yy * 8;
        float v = t[tx][ty + yy * 8];
        __half h = __float2half_rn(v);
        g_Wt[(size_t)f * 2048 + k0 + tx] = h;
        g_Wt[(size_t)f * 2048 + 1024 + k0 + tx] = __float2half_rn(v - __half2float(h));
    }
}

// Prep: c1[f] = sum_k a2[k] W[k][f];  c2[f] = sum_k b2[k] W[k][f] + b[f]
__global__ void prep_c_kernel(const float* __restrict__ a2, const float* __restrict__ b2,
                              const float* __restrict__ W, const float* __restrict__ b) {
    int f = threadIdx.x;  // 0..127
    float c1 = 0.f, c2 = 0.f;
#pragma unroll 8
    for (int k = 0; k < D2; ++k) {
        float w = W[k * FDIM + f];
        c1 += a2[k] * w;
        c2 += b2[k] * w;
    }
    g_c1[f] = c1;
    g_c2[f] = c2 + b[f];
}

// ---------------------------------------------------------------------------
extern "C" void kernel_launch(void* const* d_in, const int* in_sizes, int n_in,
                              void* d_out, int out_size) {
    const float* x_down   = (const float*)d_in[0];  // (1,256,192,32)
    const float* x_down_w = (const float*)d_in[1];
    const float* a2       = (const float*)d_in[2];  // (1024,)
    const float* b2       = (const float*)d_in[3];
    const float* W        = (const float*)d_in[4];  // (1024,128)
    const float* b        = (const float*)d_in[5];  // (128,)
    float* out = (float*)d_out;                     // (1,192,192,128)

    // Keep the L1/smem carveout high so two 48KB-smem CTAs co-reside per SM.
    cudaFuncSetAttribute(gemm1_mma, cudaFuncAttributePreferredSharedMemoryCarveout, 100);
    cudaFuncSetAttribute(gemm2_mma, cudaFuncAttributePreferredSharedMemoryCarveout, 100);

    split_xt<<<dim3(RDIM / 32, NDIM / 32, 2), 256>>>(x_down, x_down_w);
    split_wt<<<dim3(D2 / 32, FDIM / 32), 256>>>(W, a2);
    prep_c_kernel<<<1, 128>>>(a2, b2, W, b);
    gemm1_mma<<<dim3(48, 48), 256>>>();
    gemm2_mma<<<M2 / 128, 256>>>(out);
}

// round 14
// speedup vs baseline: 1.6811x; 1.1232x over previous
#include <cuda_runtime.h>
#include <cuda_fp16.h>
#include <stdint.h>

// Problem constants (B=1, N=256, L=192, J=32, d2=1024, F=128)
#define LDIM 192
#define NDIM 256      // K of GEMM1
#define RDIM 6144     // L*J  (M=N of GEMM1)
#define D2   1024     // J*J  (K of GEMM2)
#define FDIM 128      // N of GEMM2
#define M2   36864    // L*L  (M of GEMM2)

// ---------------------------------------------------------------------------
// Scratch (__device__ globals).
//   g_A  : x_down^T   single fp16, row r = 256 fp16 (512 B)
//   g_B  : x_down_w^T hi/lo fp16, row r = [256 hi | 256 lo] (1 KB)
//   g_P  : pair       single fp16, row (i*192+l) = 1024 fp16 (2 KB)
//   g_Wt : (a2*W)^T   hi/lo fp16, row f = [1024 hi | 1024 lo] (4 KB)
// ---------------------------------------------------------------------------
__device__ __half g_A[(size_t)RDIM * 256];
__device__ __half g_B[(size_t)RDIM * 512];
__device__ __half g_P[(size_t)M2 * 1024];
__device__ __half g_Wt[(size_t)FDIM * 2048];
__device__ float g_mu[M2];
__device__ float g_rs[M2];
__device__ float g_c1[FDIM];
__device__ float g_c2[FDIM];
__device__ float g_cp1[8][FDIM];   // c1 partials
__device__ float g_cp2[8][FDIM];   // c2 partials

// ---------------------------------------------------------------------------
// Family-portable PTX helpers (compute_103-safe)
// ---------------------------------------------------------------------------
__device__ __forceinline__ uint32_t smem_u32(const void* p) {
    uint32_t a;
    asm("{ .reg .u64 t; cvta.to.shared.u64 t, %1; cvt.u32.u64 %0, t; }" : "=r"(a) : "l"(p));
    return a;
}
__device__ __forceinline__ void cp16(uint32_t dst, const void* src) {
    asm volatile("cp.async.cg.shared.global [%0], [%1], 16;" :: "r"(dst), "l"(src) : "memory");
}
__device__ __forceinline__ void cp_commit() {
    asm volatile("cp.async.commit_group;" ::: "memory");
}
template <int N>
__device__ __forceinline__ void cp_wait() {
    asm volatile("cp.async.wait_group %0;" :: "n"(N) : "memory");
}
__device__ __forceinline__ void ldm4(uint32_t a[4], uint32_t addr) {
    asm volatile("ldmatrix.sync.aligned.m8n8.x4.shared.b16 {%0,%1,%2,%3}, [%4];"
                 : "=r"(a[0]), "=r"(a[1]), "=r"(a[2]), "=r"(a[3]) : "r"(addr));
}
__device__ __forceinline__ void ldm2(uint32_t b[2], uint32_t addr) {
    asm volatile("ldmatrix.sync.aligned.m8n8.x2.shared.b16 {%0,%1}, [%2];"
                 : "=r"(b[0]), "=r"(b[1]) : "r"(addr));
}
// fp16 inputs, fp32 accumulate
__device__ __forceinline__ void mma16816(float c[4], const uint32_t a[4], const uint32_t b[2]) {
    asm volatile(
        "mma.sync.aligned.m16n8k16.row.col.f32.f16.f16.f32 "
        "{%0,%1,%2,%3}, {%4,%5,%6,%7}, {%8,%9}, {%0,%1,%2,%3};"
        : "+f"(c[0]), "+f"(c[1]), "+f"(c[2]), "+f"(c[3])
        : "r"(a[0]), "r"(a[1]), "r"(a[2]), "r"(a[3]), "r"(b[0]), "r"(b[1]));
}

// SMEM subtile: 128 rows x 16 fp16 (32B/row), 2x16B chunks.
// Swizzle: chunk bit XOR (r>>2)&1 -> conflict-free ldmatrix phases.
__device__ __forceinline__ uint32_t sw(int r, int c2) {
    return (uint32_t)(r * 32 + ((c2 ^ ((r >> 2) & 1)) << 4));
}

// Stage (24 KB) = 32-K worth of data as six 4KB 16-K subtiles:
// [A_k0 | A_k1 | Bh_k0 | Bh_k1 | Bl_k0 | Bl_k1]
#define STAGE_BYTES 24576
#define SMEM_BYTES  (2 * STAGE_BYTES)   // 48 KB static, 2 stages

// ---------------------------------------------------------------------------
// Shared mainloop: 128x128 CTA tile, 8 warps (2x4), warp tile 64x32,
// 32-K per iteration, 2-stage ring, ONE wait + ONE barrier per 32-K.
// Protocol: wait<0> (only chunk c in flight, issued one iteration ago) ->
// barrier (all warps finished reading stage st^1) -> prefetch c+1 into st^1
// -> compute chunk c (two 16-K phases). 2-MMA fp16 split: A single, B=bh+bl.
// ---------------------------------------------------------------------------
template <int AROWB, int BROWB, int BLOB>
__device__ __forceinline__ void mainloop(
    uint32_t sb, int NC32,
    const char* __restrict__ A, const char* __restrict__ B,
    float acc[4][4][4])
{
    const int tid = threadIdx.x, lane = tid & 31;
    const int wr = tid >> 7;           // warp row 0..1 (64 rows each)
    const int wc = (tid >> 5) & 3;     // warp col 0..3 (32 cols each)

    // global->smem: 6 x 16B per thread per 32-K (256 threads = 128 rows x 2 chunks)
    const int r = tid >> 1, c2 = tid & 1;
    const uint32_t so = sw(r, c2);
    const char* pA = A + (size_t)r * AROWB + c2 * 16;
    const char* pB = B + (size_t)r * BROWB + c2 * 16;

    // ldmatrix fragment base offsets (+512/+256 keep (r>>2)&1 parity).
    const uint32_t abase = sw(wr * 64 + (lane & 15), lane >> 4);
    const uint32_t bbase = sw(wc * 32 + (lane & 7), (lane >> 3) & 1);

#define ISSUE_CHUNK(ck, st) do {                                   \
        uint32_t _b = sb + (uint32_t)(st) * STAGE_BYTES;           \
        int _ko = (ck) * 64;                                       \
        cp16(_b + so,           pA + _ko);                         \
        cp16(_b + 4096u + so,   pA + _ko + 32);                    \
        cp16(_b + 8192u + so,   pB + _ko);                         \
        cp16(_b + 12288u + so,  pB + _ko + 32);                    \
        cp16(_b + 16384u + so,  pB + BLOB + _ko);                  \
        cp16(_b + 20480u + so,  pB + BLOB + _ko + 32);             \
    } while (0)

    // prologue: chunk 0 -> stage 0
    ISSUE_CHUNK(0, 0); cp_commit();

#pragma unroll 1
    for (int c = 0; c < NC32; ++c) {
        const int st = c & 1;
        cp_wait<0>();          // chunk c resident (the only group in flight)
        __syncthreads();       // all warps finished reading stage st^1

        if (c + 1 < NC32) { ISSUE_CHUNK(c + 1, st ^ 1); cp_commit(); }

        const uint32_t Ab = sb + (uint32_t)st * STAGE_BYTES;
#pragma unroll
        for (int k = 0; k < 2; ++k) {
            const uint32_t Ak  = Ab + (uint32_t)k * 4096u;
            const uint32_t Bkh = Ab + 8192u + (uint32_t)k * 4096u;
            const uint32_t Bkl = Ab + 16384u + (uint32_t)k * 4096u;

            uint32_t bh[4][2], bl[4][2];
#pragma unroll
            for (int nt = 0; nt < 4; ++nt) {
                ldm2(bh[nt], Bkh + bbase + nt * 256u);
                ldm2(bl[nt], Bkl + bbase + nt * 256u);
            }
#pragma unroll
            for (int mt = 0; mt < 4; ++mt) {
                uint32_t a[4];
                ldm4(a, Ak + abase + mt * 512u);
#pragma unroll
                for (int nt = 0; nt < 4; ++nt) mma16816(acc[mt][nt], a, bh[nt]);
#pragma unroll
                for (int nt = 0; nt < 4; ++nt) mma16816(acc[mt][nt], a, bl[nt]);
            }
        }
    }
#undef ISSUE_CHUNK
}

// ---------------------------------------------------------------------------
// GEMM1: pair(6144x6144) = Xd^T Xw, K=256. Epilogue: LN stats per 32x32
// (i,l) block + pair stored single fp16 in GEMM2 layout.
// ---------------------------------------------------------------------------
__global__ __launch_bounds__(256, 2) void gemm1_mma() {
    __shared__ char smem[SMEM_BYTES];
    const uint32_t sb = smem_u32(smem);

    float acc[4][4][4];
#pragma unroll
    for (int a = 0; a < 4; ++a)
#pragma unroll
        for (int b = 0; b < 4; ++b)
#pragma unroll
            for (int d = 0; d < 4; ++d) acc[a][b][d] = 0.f;

    const int r0 = blockIdx.y * 128, c0 = blockIdx.x * 128;
    mainloop<512, 1024, 512>(sb, NDIM / 32,
                             (const char*)g_A + (size_t)r0 * 512,
                             (const char*)g_B + (size_t)c0 * 1024, acc);

    const int tid = threadIdx.x, lane = tid & 31;
    const int wr = tid >> 7, wc = (tid >> 5) & 3;

    // Warp covers rows wr*64..+63 (2 LN i-blocks), cols wc*32..+31 (1 l-block).
#pragma unroll
    for (int b = 0; b < 2; ++b) {
        float s = 0.f, q = 0.f;
#pragma unroll
        for (int mt2 = 0; mt2 < 2; ++mt2)
#pragma unroll
            for (int nt = 0; nt < 4; ++nt)
#pragma unroll
                for (int d = 0; d < 4; ++d) {
                    float v = acc[b * 2 + mt2][nt][d];
                    s += v;
                    q += v * v;
                }
#pragma unroll
        for (int o = 16; o; o >>= 1) {
            s += __shfl_xor_sync(0xFFFFFFFFu, s, o);
            q += __shfl_xor_sync(0xFFFFFFFFu, q, o);
        }
        const int i = blockIdx.y * 4 + wr * 2 + b;
        const int l = blockIdx.x * 4 + wc;
        if (lane == 0) {
            float mean = s * (1.0f / 1024.0f);
            float var = q * (1.0f / 1024.0f) - mean * mean;
            g_mu[i * LDIM + l] = mean;
            g_rs[i * LDIM + l] = rsqrtf(var + 1e-5f);
        }
        const size_t ro = (size_t)(i * LDIM + l) * 1024;   // fp16 row
#pragma unroll
        for (int mt2 = 0; mt2 < 2; ++mt2)
#pragma unroll
            for (int nt = 0; nt < 4; ++nt)
#pragma unroll
                for (int h = 0; h < 2; ++h) {
                    float v0 = acc[b * 2 + mt2][nt][h * 2 + 0];
                    float v1 = acc[b * 2 + mt2][nt][h * 2 + 1];
                    int j = mt2 * 16 + (lane >> 2) + 8 * h;
                    int m = nt * 8 + (lane & 3) * 2;
                    __half2 hh = __floats2half2_rn(v0, v1);
                    *(uint32_t*)(g_P + ro + j * 32 + m) = *(uint32_t*)&hh;
                }
    }
}

// ---------------------------------------------------------------------------
// GEMM2: out(36864x128) = pair @ Wp, K=1024. Epilogue: folded layernorm.
// A = pair (single fp16), B = Wt (hi/lo).
// ---------------------------------------------------------------------------
__global__ __launch_bounds__(256, 2) void gemm2_mma(float* __restrict__ out) {
    __shared__ char smem[SMEM_BYTES];
    const uint32_t sb = smem_u32(smem);

    float acc[4][4][4];
#pragma unroll
    for (int a = 0; a < 4; ++a)
#pragma unroll
        for (int b = 0; b < 4; ++b)
#pragma unroll
            for (int d = 0; d < 4; ++d) acc[a][b][d] = 0.f;

    const int row0 = blockIdx.x * 128;
    mainloop<2048, 4096, 2048>(sb, D2 / 32,
                               (const char*)g_P + (size_t)row0 * 2048,
                               (const char*)g_Wt, acc);

    const int tid = threadIdx.x, lane = tid & 31;
    const int wr = tid >> 7, wc = (tid >> 5) & 3;

    float c1v[4][2], c2v[4][2];
#pragma unroll
    for (int nt = 0; nt < 4; ++nt)
#pragma unroll
        for (int e = 0; e < 2; ++e) {
            int f = wc * 32 + nt * 8 + (lane & 3) * 2 + e;
            c1v[nt][e] = g_c1[f];
            c2v[nt][e] = g_c2[f];
        }
#pragma unroll
    for (int mt = 0; mt < 4; ++mt)
#pragma unroll
        for (int h = 0; h < 2; ++h) {
            int rr = row0 + wr * 64 + mt * 16 + (lane >> 2) + 8 * h;
            float rs = g_rs[rr];
            float tmu = rs * g_mu[rr];
#pragma unroll
            for (int nt = 0; nt < 4; ++nt) {
                float2 o;
                o.x = rs * acc[mt][nt][h * 2 + 0] - tmu * c1v[nt][0] + c2v[nt][0];
                o.y = rs * acc[mt][nt][h * 2 + 1] - tmu * c1v[nt][1] + c2v[nt][1];
                *(float2*)(out + (size_t)rr * FDIM + wc * 32 + nt * 8 + (lane & 3) * 2) = o;
            }
        }
}

// ---------------------------------------------------------------------------
// Prep: transpose x_down / x_down_w (256 x 6144 -> 6144 rows).
// z=0: x_down -> g_A single fp16.  z=1: x_down_w -> g_B fp16 hi|lo.
// ---------------------------------------------------------------------------
__global__ __launch_bounds__(256) void split_xt(const float* __restrict__ xd,
                                                const float* __restrict__ xw) {
    __shared__ float t[32][33];
    const float* src = blockIdx.z ? xw : xd;
    const int r0 = blockIdx.x * 32, n0 = blockIdx.y * 32;
    const int tx = threadIdx.x & 31, ty = threadIdx.x >> 5;
#pragma unroll
    for (int yy = 0; yy < 4; ++yy) {
        int n = n0 + ty + yy * 8;
        t[ty + yy * 8][tx] = src[(size_t)n * RDIM + r0 + tx];
    }
    __syncthreads();
#pragma unroll
    for (int yy = 0; yy < 4; ++yy) {
        int r = r0 + ty + yy * 8;
        float v = t[tx][ty + yy * 8];
        __half h = __float2half_rn(v);
        if (blockIdx.z == 0) {
            g_A[(size_t)r * 256 + n0 + tx] = h;
        } else {
            g_B[(size_t)r * 512 + n0 + tx] = h;
            g_B[(size_t)r * 512 + 256 + n0 + tx] = __float2half_rn(v - __half2float(h));
        }
    }
}

// Prep: Wp^T = (a2 (.) W)^T, fp16 hi/lo, layout [f][k-hi | k-lo]
__global__ __launch_bounds__(256) void split_wt(const float* __restrict__ W,
                                                const float* __restrict__ a2) {
    __shared__ float t[32][33];
    const int k0 = blockIdx.x * 32, f0 = blockIdx.y * 32;
    const int tx = threadIdx.x & 31, ty = threadIdx.x >> 5;
#pragma unroll
    for (int yy = 0; yy < 4; ++yy) {
        int k = k0 + ty + yy * 8;
        t[ty + yy * 8][tx] = a2[k] * W[(size_t)k * FDIM + f0 + tx];
    }
    __syncthreads();
#pragma unroll
    for (int yy = 0; yy < 4; ++yy) {
        int f = f0 + ty + yy * 8;
        float v = t[tx][ty + yy * 8];
        __half h = __float2half_rn(v);
        g_Wt[(size_t)f * 2048 + k0 + tx] = h;
        g_Wt[(size_t)f * 2048 + 1024 + k0 + tx] = __float2half_rn(v - __half2float(h));
    }
}

// Prep pass 1 (parallel, coalesced): block b sums k in [b*128, b*128+128).
// thread t: f = t&127, k-slice = t>>7 (64 k each). No atomics (deterministic).
__global__ __launch_bounds__(256) void prep_c_part(const float* __restrict__ a2,
                                                   const float* __restrict__ b2,
                                                   const float* __restrict__ W) {
    __shared__ float s1[2][FDIM], s2[2][FDIM];
    const int f = threadIdx.x & 127, ks = threadIdx.x >> 7;
    const int kbase = blockIdx.x * 128 + ks * 64;
    float c1 = 0.f, c2 = 0.f;
#pragma unroll 8
    for (int kk = 0; kk < 64; ++kk) {
        int k = kbase + kk;
        float w = W[(size_t)k * FDIM + f];
        c1 += a2[k] * w;
        c2 += b2[k] * w;
    }
    s1[ks][f] = c1;
    s2[ks][f] = c2;
    __syncthreads();
    if (ks == 0) {
        g_cp1[blockIdx.x][f] = s1[0][f] + s1[1][f];
        g_cp2[blockIdx.x][f] = s2[0][f] + s2[1][f];
    }
}

// Prep pass 2: reduce the 8 partials.
__global__ void prep_c_final(const float* __restrict__ b) {
    int f = threadIdx.x;  // 0..127
    float c1 = 0.f, c2 = 0.f;
#pragma unroll
    for (int p = 0; p < 8; ++p) {
        c1 += g_cp1[p][f];
        c2 += g_cp2[p][f];
    }
    g_c1[f] = c1;
    g_c2[f] = c2 + b[f];
}

// ---------------------------------------------------------------------------
extern "C" void kernel_launch(void* const* d_in, const int* in_sizes, int n_in,
                              void* d_out, int out_size) {
    const float* x_down   = (const float*)d_in[0];  // (1,256,192,32)
    const float* x_down_w = (const float*)d_in[1];
    const float* a2       = (const float*)d_in[2];  // (1024,)
    const float* b2       = (const float*)d_in[3];
    const float* W        = (const float*)d_in[4];  // (1024,128)
    const float* b        = (const float*)d_in[5];  // (128,)
    float* out = (float*)d_out;                     // (1,192,192,128)

    // Keep the L1/smem carveout high so two 48KB-smem CTAs co-reside per SM.
    cudaFuncSetAttribute(gemm1_mma, cudaFuncAttributePreferredSharedMemoryCarveout, 100);
    cudaFuncSetAttribute(gemm2_mma, cudaFuncAttributePreferredSharedMemoryCarveout, 100);

    split_xt<<<dim3(RDIM / 32, NDIM / 32, 2), 256>>>(x_down, x_down_w);
    split_wt<<<dim3(D2 / 32, FDIM / 32), 256>>>(W, a2);
    prep_c_part<<<8, 256>>>(a2, b2, W);
    prep_c_final<<<1, 128>>>(b);
    gemm1_mma<<<dim3(48, 48), 256>>>();
    gemm2_mma<<<M2 / 128, 256>>>(out);
}

// round 15
// speedup vs baseline: 2.2258x; 1.3240x over previous
#include <cuda_runtime.h>
#include <cuda_fp16.h>
#include <stdint.h>

// Problem constants (B=1, N=256, L=192, J=32, d2=1024, F=128)
#define LDIM 192
#define NDIM 256      // K of GEMM1
#define RDIM 6144     // L*J  (M=N of GEMM1)
#define D2   1024     // J*J  (K of GEMM2)
#define FDIM 128      // N of GEMM2
#define M2   36864    // L*L  (M of GEMM2)

// ---------------------------------------------------------------------------
// Scratch (__device__ globals). ALL operands single fp16 now.
//   g_A  : x_down^T   row r = 256 fp16 (512 B)
//   g_B  : x_down_w^T row r = 256 fp16 (512 B)
//   g_P  : pair       row (i*192+l) = 1024 fp16 (2 KB)
//   g_Wt : (a2*W)^T   row f = 1024 fp16 (2 KB)
// ---------------------------------------------------------------------------
__device__ __half g_A[(size_t)RDIM * 256];
__device__ __half g_B[(size_t)RDIM * 256];
__device__ __half g_P[(size_t)M2 * 1024];
__device__ __half g_Wt[(size_t)FDIM * 1024];
__device__ float g_mu[M2];
__device__ float g_rs[M2];
__device__ float g_c1[FDIM];
__device__ float g_c2[FDIM];

// ---------------------------------------------------------------------------
// Family-portable PTX helpers (compute_103-safe)
// ---------------------------------------------------------------------------
__device__ __forceinline__ uint32_t smem_u32(const void* p) {
    uint32_t a;
    asm("{ .reg .u64 t; cvta.to.shared.u64 t, %1; cvt.u32.u64 %0, t; }" : "=r"(a) : "l"(p));
    return a;
}
__device__ __forceinline__ void cp16(uint32_t dst, const void* src) {
    asm volatile("cp.async.cg.shared.global [%0], [%1], 16;" :: "r"(dst), "l"(src) : "memory");
}
__device__ __forceinline__ void cp_commit() {
    asm volatile("cp.async.commit_group;" ::: "memory");
}
template <int N>
__device__ __forceinline__ void cp_wait() {
    asm volatile("cp.async.wait_group %0;" :: "n"(N) : "memory");
}
__device__ __forceinline__ void ldm4(uint32_t a[4], uint32_t addr) {
    asm volatile("ldmatrix.sync.aligned.m8n8.x4.shared.b16 {%0,%1,%2,%3}, [%4];"
                 : "=r"(a[0]), "=r"(a[1]), "=r"(a[2]), "=r"(a[3]) : "r"(addr));
}
__device__ __forceinline__ void ldm2(uint32_t b[2], uint32_t addr) {
    asm volatile("ldmatrix.sync.aligned.m8n8.x2.shared.b16 {%0,%1}, [%2];"
                 : "=r"(b[0]), "=r"(b[1]) : "r"(addr));
}
// fp16 inputs, fp32 accumulate
__device__ __forceinline__ void mma16816(float c[4], const uint32_t a[4], const uint32_t b[2]) {
    asm volatile(
        "mma.sync.aligned.m16n8k16.row.col.f32.f16.f16.f32 "
        "{%0,%1,%2,%3}, {%4,%5,%6,%7}, {%8,%9}, {%0,%1,%2,%3};"
        : "+f"(c[0]), "+f"(c[1]), "+f"(c[2]), "+f"(c[3])
        : "r"(a[0]), "r"(a[1]), "r"(a[2]), "r"(a[3]), "r"(b[0]), "r"(b[1]));
}

// SMEM subtile: 128 rows x 16 fp16 (32B/row), 2x16B chunks.
// Swizzle: chunk bit XOR (r>>2)&1 -> conflict-free ldmatrix phases.
__device__ __forceinline__ uint32_t sw(int r, int c2) {
    return (uint32_t)(r * 32 + ((c2 ^ ((r >> 2) & 1)) << 4));
}

// Stage (16 KB) = 32-K worth: [A_k0 | A_k1 | B_k0 | B_k1] (4KB subtiles)
#define STAGE_BYTES 16384
#define SMEM_BYTES  (2 * STAGE_BYTES)   // 32 KB static, 2 stages

// ---------------------------------------------------------------------------
// Shared mainloop: 128x128 CTA tile, 8 warps (2x4), warp tile 64x32,
// 32-K per iteration, 2-stage ring, ONE wait + ONE barrier per 32-K
// (R14-validated protocol). Single fp16 operands: 1 MMA per k-step.
// ---------------------------------------------------------------------------
template <int AROWB, int BROWB>
__device__ __forceinline__ void mainloop(
    uint32_t sb, int NC32,
    const char* __restrict__ A, const char* __restrict__ B,
    float acc[4][4][4])
{
    const int tid = threadIdx.x, lane = tid & 31;
    const int wr = tid >> 7;           // warp row 0..1 (64 rows each)
    const int wc = (tid >> 5) & 3;     // warp col 0..3 (32 cols each)

    // global->smem: 4 x 16B per thread per 32-K (256 threads = 128 rows x 2 chunks)
    const int r = tid >> 1, c2 = tid & 1;
    const uint32_t so = sw(r, c2);
    const char* pA = A + (size_t)r * AROWB + c2 * 16;
    const char* pB = B + (size_t)r * BROWB + c2 * 16;

    // ldmatrix fragment base offsets (+512/+256 shift rows by 16/8: parity safe).
    const uint32_t abase = sw(wr * 64 + (lane & 15), lane >> 4);
    const uint32_t bbase = sw(wc * 32 + (lane & 7), (lane >> 3) & 1);

#define ISSUE_CHUNK(ck, st) do {                                   \
        uint32_t _b = sb + (uint32_t)(st) * STAGE_BYTES;           \
        int _ko = (ck) * 64;                                       \
        cp16(_b + so,           pA + _ko);                         \
        cp16(_b + 4096u + so,   pA + _ko + 32);                    \
        cp16(_b + 8192u + so,   pB + _ko);                         \
        cp16(_b + 12288u + so,  pB + _ko + 32);                    \
    } while (0)

    // prologue: chunk 0 -> stage 0
    ISSUE_CHUNK(0, 0); cp_commit();

#pragma unroll 1
    for (int c = 0; c < NC32; ++c) {
        const int st = c & 1;
        cp_wait<0>();          // chunk c resident (the only group in flight)
        __syncthreads();       // all warps finished reading stage st^1

        if (c + 1 < NC32) { ISSUE_CHUNK(c + 1, st ^ 1); cp_commit(); }

        const uint32_t Ab = sb + (uint32_t)st * STAGE_BYTES;
#pragma unroll
        for (int k = 0; k < 2; ++k) {
            const uint32_t Ak = Ab + (uint32_t)k * 4096u;
            const uint32_t Bk = Ab + 8192u + (uint32_t)k * 4096u;

            uint32_t bf[4][2];
#pragma unroll
            for (int nt = 0; nt < 4; ++nt) ldm2(bf[nt], Bk + bbase + nt * 256u);
#pragma unroll
            for (int mt = 0; mt < 4; ++mt) {
                uint32_t a[4];
                ldm4(a, Ak + abase + mt * 512u);
#pragma unroll
                for (int nt = 0; nt < 4; ++nt) mma16816(acc[mt][nt], a, bf[nt]);
            }
        }
    }
#undef ISSUE_CHUNK
}

// ---------------------------------------------------------------------------
// GEMM1: pair(6144x6144) = Xd^T Xw, K=256. Epilogue: LN stats per 32x32
// (i,l) block + pair stored single fp16 in GEMM2 layout.
// ---------------------------------------------------------------------------
__global__ __launch_bounds__(256, 2) void gemm1_mma() {
    __shared__ char smem[SMEM_BYTES];
    const uint32_t sb = smem_u32(smem);

    float acc[4][4][4];
#pragma unroll
    for (int a = 0; a < 4; ++a)
#pragma unroll
        for (int b = 0; b < 4; ++b)
#pragma unroll
            for (int d = 0; d < 4; ++d) acc[a][b][d] = 0.f;

    const int r0 = blockIdx.y * 128, c0 = blockIdx.x * 128;
    mainloop<512, 512>(sb, NDIM / 32,
                       (const char*)g_A + (size_t)r0 * 512,
                       (const char*)g_B + (size_t)c0 * 512, acc);

    const int tid = threadIdx.x, lane = tid & 31;
    const int wr = tid >> 7, wc = (tid >> 5) & 3;

    // Warp covers rows wr*64..+63 (2 LN i-blocks), cols wc*32..+31 (1 l-block).
#pragma unroll
    for (int b = 0; b < 2; ++b) {
        float s = 0.f, q = 0.f;
#pragma unroll
        for (int mt2 = 0; mt2 < 2; ++mt2)
#pragma unroll
            for (int nt = 0; nt < 4; ++nt)
#pragma unroll
                for (int d = 0; d < 4; ++d) {
                    float v = acc[b * 2 + mt2][nt][d];
                    s += v;
                    q += v * v;
                }
#pragma unroll
        for (int o = 16; o; o >>= 1) {
            s += __shfl_xor_sync(0xFFFFFFFFu, s, o);
            q += __shfl_xor_sync(0xFFFFFFFFu, q, o);
        }
        const int i = blockIdx.y * 4 + wr * 2 + b;
        const int l = blockIdx.x * 4 + wc;
        if (lane == 0) {
            float mean = s * (1.0f / 1024.0f);
            float var = q * (1.0f / 1024.0f) - mean * mean;
            g_mu[i * LDIM + l] = mean;
            g_rs[i * LDIM + l] = rsqrtf(var + 1e-5f);
        }
        const size_t ro = (size_t)(i * LDIM + l) * 1024;   // fp16 row
#pragma unroll
        for (int mt2 = 0; mt2 < 2; ++mt2)
#pragma unroll
            for (int nt = 0; nt < 4; ++nt)
#pragma unroll
                for (int h = 0; h < 2; ++h) {
                    float v0 = acc[b * 2 + mt2][nt][h * 2 + 0];
                    float v1 = acc[b * 2 + mt2][nt][h * 2 + 1];
                    int j = mt2 * 16 + (lane >> 2) + 8 * h;
                    int m = nt * 8 + (lane & 3) * 2;
                    __half2 hh = __floats2half2_rn(v0, v1);
                    *(uint32_t*)(g_P + ro + j * 32 + m) = *(uint32_t*)&hh;
                }
    }
}

// ---------------------------------------------------------------------------
// GEMM2: out(36864x128) = pair @ Wp, K=1024. Epilogue: folded layernorm.
// ---------------------------------------------------------------------------
__global__ __launch_bounds__(256, 2) void gemm2_mma(float* __restrict__ out) {
    __shared__ char smem[SMEM_BYTES];
    const uint32_t sb = smem_u32(smem);

    float acc[4][4][4];
#pragma unroll
    for (int a = 0; a < 4; ++a)
#pragma unroll
        for (int b = 0; b < 4; ++b)
#pragma unroll
            for (int d = 0; d < 4; ++d) acc[a][b][d] = 0.f;

    const int row0 = blockIdx.x * 128;
    mainloop<2048, 2048>(sb, D2 / 32,
                         (const char*)g_P + (size_t)row0 * 2048,
                         (const char*)g_Wt, acc);

    const int tid = threadIdx.x, lane = tid & 31;
    const int wr = tid >> 7, wc = (tid >> 5) & 3;

    float c1v[4][2], c2v[4][2];
#pragma unroll
    for (int nt = 0; nt < 4; ++nt)
#pragma unroll
        for (int e = 0; e < 2; ++e) {
            int f = wc * 32 + nt * 8 + (lane & 3) * 2 + e;
            c1v[nt][e] = g_c1[f];
            c2v[nt][e] = g_c2[f];
        }
#pragma unroll
    for (int mt = 0; mt < 4; ++mt)
#pragma unroll
        for (int h = 0; h < 2; ++h) {
            int rr = row0 + wr * 64 + mt * 16 + (lane >> 2) + 8 * h;
            float rs = g_rs[rr];
            float tmu = rs * g_mu[rr];
#pragma unroll
            for (int nt = 0; nt < 4; ++nt) {
                float2 o;
                o.x = rs * acc[mt][nt][h * 2 + 0] - tmu * c1v[nt][0] + c2v[nt][0];
                o.y = rs * acc[mt][nt][h * 2 + 1] - tmu * c1v[nt][1] + c2v[nt][1];
                *(float2*)(out + (size_t)rr * FDIM + wc * 32 + nt * 8 + (lane & 3) * 2) = o;
            }
        }
}

// ---------------------------------------------------------------------------
// Prep (merged): z=0 -> x_down^T -> g_A; z=1 -> x_down_w^T -> g_B;
// z=2 (x<32, y<4 only) -> (a2*W)^T -> g_Wt. All single fp16.
// ---------------------------------------------------------------------------
__global__ __launch_bounds__(256) void prep_split(const float* __restrict__ xd,
                                                  const float* __restrict__ xw,
                                                  const float* __restrict__ W,
                                                  const float* __restrict__ a2) {
    __shared__ float t[32][33];
    const int tx = threadIdx.x & 31, ty = threadIdx.x >> 5;

    if (blockIdx.z < 2) {
        const float* src = blockIdx.z ? xw : xd;
        __half* dst = blockIdx.z ? g_B : g_A;
        const int r0 = blockIdx.x * 32, n0 = blockIdx.y * 32;
#pragma unroll
        for (int yy = 0; yy < 4; ++yy) {
            int n = n0 + ty + yy * 8;
            t[ty + yy * 8][tx] = src[(size_t)n * RDIM + r0 + tx];
        }
        __syncthreads();
#pragma unroll
        for (int yy = 0; yy < 4; ++yy) {
            int r = r0 + ty + yy * 8;
            dst[(size_t)r * 256 + n0 + tx] = __float2half_rn(t[tx][ty + yy * 8]);
        }
    } else {
        if (blockIdx.x >= 32 || blockIdx.y >= 4) return;
        const int k0 = blockIdx.x * 32, f0 = blockIdx.y * 32;
#pragma unroll
        for (int yy = 0; yy < 4; ++yy) {
            int k = k0 + ty + yy * 8;
            t[ty + yy * 8][tx] = a2[k] * W[(size_t)k * FDIM + f0 + tx];
        }
        __syncthreads();
#pragma unroll
        for (int yy = 0; yy < 4; ++yy) {
            int f = f0 + ty + yy * 8;
            g_Wt[(size_t)f * 1024 + k0 + tx] = __float2half_rn(t[tx][ty + yy * 8]);
        }
    }
}

// Prep: c1[f] = sum_k a2[k] W[k][f]; c2[f] = sum_k b2[k] W[k][f] + b[f].
// Single block x 1024 threads: f = t&127, k-slice = t>>7 (128 k each);
// coalesced loads, smem tree reduce, no atomics (deterministic).
__global__ __launch_bounds__(1024) void prep_c(const float* __restrict__ a2,
                                               const float* __restrict__ b2,
                                               const float* __restrict__ W,
                                               const float* __restrict__ b) {
    __shared__ float s1[8][FDIM], s2[8][FDIM];
    const int f = threadIdx.x & 127, ks = threadIdx.x >> 7;
    const int kbase = ks * 128;
    float c1 = 0.f, c2 = 0.f;
#pragma unroll 8
    for (int kk = 0; kk < 128; ++kk) {
        int k = kbase + kk;
        float w = W[(size_t)k * FDIM + f];
        c1 += a2[k] * w;
        c2 += b2[k] * w;
    }
    s1[ks][f] = c1;
    s2[ks][f] = c2;
    __syncthreads();
    if (ks == 0) {
        float t1 = 0.f, t2 = 0.f;
#pragma unroll
        for (int p = 0; p < 8; ++p) {
            t1 += s1[p][f];
            t2 += s2[p][f];
        }
        g_c1[f] = t1;
        g_c2[f] = t2 + b[f];
    }
}

// ---------------------------------------------------------------------------
extern "C" void kernel_launch(void* const* d_in, const int* in_sizes, int n_in,
                              void* d_out, int out_size) {
    const float* x_down   = (const float*)d_in[0];  // (1,256,192,32)
    const float* x_down_w = (const float*)d_in[1];
    const float* a2       = (const float*)d_in[2];  // (1024,)
    const float* b2       = (const float*)d_in[3];
    const float* W        = (const float*)d_in[4];  // (1024,128)
    const float* b        = (const float*)d_in[5];  // (128,)
    float* out = (float*)d_out;                     // (1,192,192,128)

    // Keep the L1/smem carveout high so two CTAs co-reside per SM.
    cudaFuncSetAttribute(gemm1_mma, cudaFuncAttributePreferredSharedMemoryCarveout, 100);
    cudaFuncSetAttribute(gemm2_mma, cudaFuncAttributePreferredSharedMemoryCarveout, 100);

    prep_split<<<dim3(RDIM / 32, NDIM / 32, 3), 256>>>(x_down, x_down_w, W, a2);
    prep_c<<<1, 1024>>>(a2, b2, W, b);
    gemm1_mma<<<dim3(48, 48), 256>>>();
    gemm2_mma<<<M2 / 128, 256>>>(out);
}

// round 16
// speedup vs baseline: 2.2963x; 1.0317x over previous
#include <cuda_runtime.h>
#include <cuda_fp16.h>
#include <stdint.h>

// Problem constants (B=1, N=256, L=192, J=32, d2=1024, F=128)
#define LDIM 192
#define NDIM 256      // K of GEMM1
#define RDIM 6144     // L*J  (M=N of GEMM1)
#define D2   1024     // J*J  (K of GEMM2)
#define FDIM 128      // N of GEMM2
#define M2   36864    // L*L  (M of GEMM2)

// ---------------------------------------------------------------------------
// Scratch (__device__ globals). ALL operands single fp16.
// ---------------------------------------------------------------------------
__device__ __half g_A[(size_t)RDIM * 256];
__device__ __half g_B[(size_t)RDIM * 256];
__device__ __half g_P[(size_t)M2 * 1024];
__device__ __half g_Wt[(size_t)FDIM * 1024];
__device__ float g_mu[M2];
__device__ float g_rs[M2];
__device__ float g_c1[FDIM];
__device__ float g_c2[FDIM];

// ---------------------------------------------------------------------------
// Family-portable PTX helpers (compute_103-safe)
// ---------------------------------------------------------------------------
__device__ __forceinline__ uint32_t smem_u32(const void* p) {
    uint32_t a;
    asm("{ .reg .u64 t; cvta.to.shared.u64 t, %1; cvt.u32.u64 %0, t; }" : "=r"(a) : "l"(p));
    return a;
}
__device__ __forceinline__ void cp16(uint32_t dst, const void* src) {
    asm volatile("cp.async.cg.shared.global [%0], [%1], 16;" :: "r"(dst), "l"(src) : "memory");
}
__device__ __forceinline__ void cp_commit() {
    asm volatile("cp.async.commit_group;" ::: "memory");
}
template <int N>
__device__ __forceinline__ void cp_wait() {
    asm volatile("cp.async.wait_group %0;" :: "n"(N) : "memory");
}
__device__ __forceinline__ void ldm4(uint32_t a[4], uint32_t addr) {
    asm volatile("ldmatrix.sync.aligned.m8n8.x4.shared.b16 {%0,%1,%2,%3}, [%4];"
                 : "=r"(a[0]), "=r"(a[1]), "=r"(a[2]), "=r"(a[3]) : "r"(addr));
}
__device__ __forceinline__ void ldm2(uint32_t b[2], uint32_t addr) {
    asm volatile("ldmatrix.sync.aligned.m8n8.x2.shared.b16 {%0,%1}, [%2];"
                 : "=r"(b[0]), "=r"(b[1]) : "r"(addr));
}
// fp16 inputs, fp32 accumulate
__device__ __forceinline__ void mma16816(float c[4], const uint32_t a[4], const uint32_t b[2]) {
    asm volatile(
        "mma.sync.aligned.m16n8k16.row.col.f32.f16.f16.f32 "
        "{%0,%1,%2,%3}, {%4,%5,%6,%7}, {%8,%9}, {%0,%1,%2,%3};"
        : "+f"(c[0]), "+f"(c[1]), "+f"(c[2]), "+f"(c[3])
        : "r"(a[0]), "r"(a[1]), "r"(a[2]), "r"(a[3]), "r"(b[0]), "r"(b[1]));
}

// SMEM subtile: 128 rows x 16 fp16 (32B/row), 2x16B chunks.
// Swizzle: chunk bit XOR (r>>2)&1 -> conflict-free ldmatrix phases.
__device__ __forceinline__ uint32_t sw(int r, int c2) {
    return (uint32_t)(r * 32 + ((c2 ^ ((r >> 2) & 1)) << 4));
}

// Stage (16 KB) = 32-K worth: [A_k0 | A_k1 | B_k0 | B_k1] (4KB subtiles)
#define STAGE_BYTES 16384
#define NSTAGE 3
#define SMEM_BYTES  (NSTAGE * STAGE_BYTES)   // 48 KB static, 2 CTAs/SM

// ---------------------------------------------------------------------------
// Shared mainloop: 128x128 CTA tile, 8 warps (2x4), warp tile 64x32,
// 32-K per iteration, 3-STAGE ring with prefetch distance 2 (DRAM latency
// cover for gemm2's streamed pair reads), one wait + one barrier per 32-K.
// Protocol: wait<1> (chunk c resident; c+1 may be in flight) -> barrier
// (all warps done reading stage (c-1)%3) -> issue c+2 into (c+2)%3==(c-1)%3
// -> compute chunk c. Single fp16 operands: 1 MMA per k-step.
// ---------------------------------------------------------------------------
template <int AROWB, int BROWB>
__device__ __forceinline__ void mainloop(
    uint32_t sb, int NC32,
    const char* __restrict__ A, const char* __restrict__ B,
    float acc[4][4][4])
{
    const int tid = threadIdx.x, lane = tid & 31;
    const int wr = tid >> 7;           // warp row 0..1 (64 rows each)
    const int wc = (tid >> 5) & 3;     // warp col 0..3 (32 cols each)

    // global->smem: 4 x 16B per thread per 32-K (256 threads = 128 rows x 2 chunks)
    const int r = tid >> 1, c2 = tid & 1;
    const uint32_t so = sw(r, c2);
    const char* pA = A + (size_t)r * AROWB + c2 * 16;
    const char* pB = B + (size_t)r * BROWB + c2 * 16;

    // ldmatrix fragment base offsets (+512/+256 shift rows by 16/8: parity safe).
    const uint32_t abase = sw(wr * 64 + (lane & 15), lane >> 4);
    const uint32_t bbase = sw(wc * 32 + (lane & 7), (lane >> 3) & 1);

#define ISSUE_CHUNK(ck, st) do {                                   \
        uint32_t _b = sb + (uint32_t)(st) * STAGE_BYTES;           \
        int _ko = (ck) * 64;                                       \
        cp16(_b + so,           pA + _ko);                         \
        cp16(_b + 4096u + so,   pA + _ko + 32);                    \
        cp16(_b + 8192u + so,   pB + _ko);                         \
        cp16(_b + 12288u + so,  pB + _ko + 32);                    \
    } while (0)

    // prologue: chunks 0,1 -> stages 0,1
    ISSUE_CHUNK(0, 0); cp_commit();
    if (NC32 > 1) ISSUE_CHUNK(1, 1);
    cp_commit();

#pragma unroll 1
    for (int c = 0; c < NC32; ++c) {
        const int st = c % NSTAGE;
        cp_wait<1>();          // chunk c resident (c+1 may still be in flight)
        __syncthreads();       // all warps finished reading stage (c-1)%3

        if (c + 2 < NC32) ISSUE_CHUNK(c + 2, (c + 2) % NSTAGE);
        cp_commit();

        const uint32_t Ab = sb + (uint32_t)st * STAGE_BYTES;
#pragma unroll
        for (int k = 0; k < 2; ++k) {
            const uint32_t Ak = Ab + (uint32_t)k * 4096u;
            const uint32_t Bk = Ab + 8192u + (uint32_t)k * 4096u;

            uint32_t bf[4][2];
#pragma unroll
            for (int nt = 0; nt < 4; ++nt) ldm2(bf[nt], Bk + bbase + nt * 256u);
#pragma unroll
            for (int mt = 0; mt < 4; ++mt) {
                uint32_t a[4];
                ldm4(a, Ak + abase + mt * 512u);
#pragma unroll
                for (int nt = 0; nt < 4; ++nt) mma16816(acc[mt][nt], a, bf[nt]);
            }
        }
    }
#undef ISSUE_CHUNK
}

// ---------------------------------------------------------------------------
// GEMM1: pair(6144x6144) = Xd^T Xw, K=256. Epilogue: LN stats per 32x32
// (i,l) block + pair stored single fp16 in GEMM2 layout.
// ---------------------------------------------------------------------------
__global__ __launch_bounds__(256, 2) void gemm1_mma() {
    __shared__ char smem[SMEM_BYTES];
    const uint32_t sb = smem_u32(smem);

    float acc[4][4][4];
#pragma unroll
    for (int a = 0; a < 4; ++a)
#pragma unroll
        for (int b = 0; b < 4; ++b)
#pragma unroll
            for (int d = 0; d < 4; ++d) acc[a][b][d] = 0.f;

    const int r0 = blockIdx.y * 128, c0 = blockIdx.x * 128;
    mainloop<512, 512>(sb, NDIM / 32,
                       (const char*)g_A + (size_t)r0 * 512,
                       (const char*)g_B + (size_t)c0 * 512, acc);

    const int tid = threadIdx.x, lane = tid & 31;
    const int wr = tid >> 7, wc = (tid >> 5) & 3;

    // Warp covers rows wr*64..+63 (2 LN i-blocks), cols wc*32..+31 (1 l-block).
#pragma unroll
    for (int b = 0; b < 2; ++b) {
        float s = 0.f, q = 0.f;
#pragma unroll
        for (int mt2 = 0; mt2 < 2; ++mt2)
#pragma unroll
            for (int nt = 0; nt < 4; ++nt)
#pragma unroll
                for (int d = 0; d < 4; ++d) {
                    float v = acc[b * 2 + mt2][nt][d];
                    s += v;
                    q += v * v;
                }
#pragma unroll
        for (int o = 16; o; o >>= 1) {
            s += __shfl_xor_sync(0xFFFFFFFFu, s, o);
            q += __shfl_xor_sync(0xFFFFFFFFu, q, o);
        }
        const int i = blockIdx.y * 4 + wr * 2 + b;
        const int l = blockIdx.x * 4 + wc;
        if (lane == 0) {
            float mean = s * (1.0f / 1024.0f);
            float var = q * (1.0f / 1024.0f) - mean * mean;
            g_mu[i * LDIM + l] = mean;
            g_rs[i * LDIM + l] = rsqrtf(var + 1e-5f);
        }
        const size_t ro = (size_t)(i * LDIM + l) * 1024;   // fp16 row
#pragma unroll
        for (int mt2 = 0; mt2 < 2; ++mt2)
#pragma unroll
            for (int nt = 0; nt < 4; ++nt)
#pragma unroll
                for (int h = 0; h < 2; ++h) {
                    float v0 = acc[b * 2 + mt2][nt][h * 2 + 0];
                    float v1 = acc[b * 2 + mt2][nt][h * 2 + 1];
                    int j = mt2 * 16 + (lane >> 2) + 8 * h;
                    int m = nt * 8 + (lane & 3) * 2;
                    __half2 hh = __floats2half2_rn(v0, v1);
                    *(uint32_t*)(g_P + ro + j * 32 + m) = *(uint32_t*)&hh;
                }
    }
}

// ---------------------------------------------------------------------------
// GEMM2: out(36864x128) = pair @ Wp, K=1024. Epilogue: folded layernorm.
// ---------------------------------------------------------------------------
__global__ __launch_bounds__(256, 2) void gemm2_mma(float* __restrict__ out) {
    __shared__ char smem[SMEM_BYTES];
    const uint32_t sb = smem_u32(smem);

    float acc[4][4][4];
#pragma unroll
    for (int a = 0; a < 4; ++a)
#pragma unroll
        for (int b = 0; b < 4; ++b)
#pragma unroll
            for (int d = 0; d < 4; ++d) acc[a][b][d] = 0.f;

    const int row0 = blockIdx.x * 128;
    mainloop<2048, 2048>(sb, D2 / 32,
                         (const char*)g_P + (size_t)row0 * 2048,
                         (const char*)g_Wt, acc);

    const int tid = threadIdx.x, lane = tid & 31;
    const int wr = tid >> 7, wc = (tid >> 5) & 3;

    float c1v[4][2], c2v[4][2];
#pragma unroll
    for (int nt = 0; nt < 4; ++nt)
#pragma unroll
        for (int e = 0; e < 2; ++e) {
            int f = wc * 32 + nt * 8 + (lane & 3) * 2 + e;
            c1v[nt][e] = g_c1[f];
            c2v[nt][e] = g_c2[f];
        }
#pragma unroll
    for (int mt = 0; mt < 4; ++mt)
#pragma unroll
        for (int h = 0; h < 2; ++h) {
            int rr = row0 + wr * 64 + mt * 16 + (lane >> 2) + 8 * h;
            float rs = g_rs[rr];
            float tmu = rs * g_mu[rr];
#pragma unroll
            for (int nt = 0; nt < 4; ++nt) {
                float2 o;
                o.x = rs * acc[mt][nt][h * 2 + 0] - tmu * c1v[nt][0] + c2v[nt][0];
                o.y = rs * acc[mt][nt][h * 2 + 1] - tmu * c1v[nt][1] + c2v[nt][1];
                *(float2*)(out + (size_t)rr * FDIM + wc * 32 + nt * 8 + (lane & 3) * 2) = o;
            }
        }
}

// ---------------------------------------------------------------------------
// Prep (merged): z=0 -> x_down^T -> g_A; z=1 -> x_down_w^T -> g_B;
// z=2 (x<32, y<4 only) -> (a2*W)^T -> g_Wt. All single fp16.
// ---------------------------------------------------------------------------
__global__ __launch_bounds__(256) void prep_split(const float* __restrict__ xd,
                                                  const float* __restrict__ xw,
                                                  const float* __restrict__ W,
                                                  const float* __restrict__ a2) {
    __shared__ float t[32][33];
    const int tx = threadIdx.x & 31, ty = threadIdx.x >> 5;

    if (blockIdx.z < 2) {
        const float* src = blockIdx.z ? xw : xd;
        __half* dst = blockIdx.z ? g_B : g_A;
        const int r0 = blockIdx.x * 32, n0 = blockIdx.y * 32;
#pragma unroll
        for (int yy = 0; yy < 4; ++yy) {
            int n = n0 + ty + yy * 8;
            t[ty + yy * 8][tx] = src[(size_t)n * RDIM + r0 + tx];
        }
        __syncthreads();
#pragma unroll
        for (int yy = 0; yy < 4; ++yy) {
            int r = r0 + ty + yy * 8;
            dst[(size_t)r * 256 + n0 + tx] = __float2half_rn(t[tx][ty + yy * 8]);
        }
    } else {
        if (blockIdx.x >= 32 || blockIdx.y >= 4) return;
        const int k0 = blockIdx.x * 32, f0 = blockIdx.y * 32;
#pragma unroll
        for (int yy = 0; yy < 4; ++yy) {
            int k = k0 + ty + yy * 8;
            t[ty + yy * 8][tx] = a2[k] * W[(size_t)k * FDIM + f0 + tx];
        }
        __syncthreads();
#pragma unroll
        for (int yy = 0; yy < 4; ++yy) {
            int f = f0 + ty + yy * 8;
            g_Wt[(size_t)f * 1024 + k0 + tx] = __float2half_rn(t[tx][ty + yy * 8]);
        }
    }
}

// Prep: c1[f] = sum_k a2[k] W[k][f]; c2[f] = sum_k b2[k] W[k][f] + b[f].
// One 1024-thread block: f = t&127, k-slice = t>>7; coalesced, deterministic.
__global__ __launch_bounds__(1024) void prep_c(const float* __restrict__ a2,
                                               const float* __restrict__ b2,
                                               const float* __restrict__ W,
                                               const float* __restrict__ b) {
    __shared__ float s1[8][FDIM], s2[8][FDIM];
    const int f = threadIdx.x & 127, ks = threadIdx.x >> 7;
    const int kbase = ks * 128;
    float c1 = 0.f, c2 = 0.f;
#pragma unroll 8
    for (int kk = 0; kk < 128; ++kk) {
        int k = kbase + kk;
        float w = W[(size_t)k * FDIM + f];
        c1 += a2[k] * w;
        c2 += b2[k] * w;
    }
    s1[ks][f] = c1;
    s2[ks][f] = c2;
    __syncthreads();
    if (ks == 0) {
        float t1 = 0.f, t2 = 0.f;
#pragma unroll
        for (int p = 0; p < 8; ++p) {
            t1 += s1[p][f];
            t2 += s2[p][f];
        }
        g_c1[f] = t1;
        g_c2[f] = t2 + b[f];
    }
}

// ---------------------------------------------------------------------------
extern "C" void kernel_launch(void* const* d_in, const int* in_sizes, int n_in,
                              void* d_out, int out_size) {
    const float* x_down   = (const float*)d_in[0];  // (1,256,192,32)
    const float* x_down_w = (const float*)d_in[1];
    const float* a2       = (const float*)d_in[2];  // (1024,)
    const float* b2       = (const float*)d_in[3];
    const float* W        = (const float*)d_in[4];  // (1024,128)
    const float* b        = (const float*)d_in[5];  // (128,)
    float* out = (float*)d_out;                     // (1,192,192,128)

    // Keep the L1/smem carveout high so two 48KB-smem CTAs co-reside per SM.
    cudaFuncSetAttribute(gemm1_mma, cudaFuncAttributePreferredSharedMemoryCarveout, 100);
    cudaFuncSetAttribute(gemm2_mma, cudaFuncAttributePreferredSharedMemoryCarveout, 100);

    prep_split<<<dim3(RDIM / 32, NDIM / 32, 3), 256>>>(x_down, x_down_w, W, a2);
    prep_c<<<1, 1024>>>(a2, b2, W, b);
    gemm1_mma<<<dim3(48, 48), 256>>>();
    gemm2_mma<<<M2 / 128, 256>>>(out);
}